// round 6
// baseline (speedup 1.0000x reference)
#include <cuda_runtime.h>
#include <cuda_fp16.h>
#include <cstdint>

// LightGCN propagation, pull formulation, fp16 storage / fp32 accumulate:
//   h0 = fp16(concat(user, item))
//   h1 = fp16(A h0) ; h2 = fp16(A h1)
//   out = 0.25 * (x0_fp32 + h1 + h2 + A h2)
// Pull kernels use 8 threads/node, 16B fp16 gathers, unroll-8 edge loop.

#define N_USERS   100000
#define N_ITEMS   50000
#define N_TOTAL   150000
#define EMB_DIM   64
#define N_EDGES   2000000
#define N_ELEMS   (N_TOTAL * EMB_DIM)
#define N_F4      (N_ELEMS / 4)            // 2,400,000 (uint2 units for prep)
#define N_U4      (N_ELEMS / 8)            // 1,200,000 (uint4 units per buffer)

#define SCAN_BLK  1024
#define N_SCANBLK ((N_TOTAL + SCAN_BLK - 1) / SCAN_BLK)   // 147

// fp16 feature buffers: 64 halves = 8 uint4 per row (19.2 MB each)
__device__ uint4 g_h0[N_U4];
__device__ uint4 g_h1[N_U4];
__device__ uint4 g_h2[N_U4];

// CSR scratch
__device__ int   g_deg[N_TOTAL];
__device__ int   g_incl[N_TOTAL];
__device__ int   g_off[N_TOTAL + 1];
__device__ int   g_cursor[N_TOTAL];
__device__ int   g_partials[N_SCANBLK];
__device__ int   g_blockoff[N_SCANBLK];
__device__ int2  g_cw[N_EDGES];            // packed {col, weight-bits}, row-sorted

__device__ int   g_idx_is64;

// ---------------------------------------------------------------------------
__device__ __forceinline__ uint2 pack_h4(float4 v) {
    __half2 a = __float22half2_rn(make_float2(v.x, v.y));
    __half2 b = __float22half2_rn(make_float2(v.z, v.w));
    uint2 r;
    r.x = *(unsigned int*)&a;
    r.y = *(unsigned int*)&b;
    return r;
}

// ---------------------------------------------------------------------------
// dtype detect (block 0) + zero histogram + convert x0 -> fp16
// ---------------------------------------------------------------------------
__global__ void prep_kernel(const long long* __restrict__ ei64,
                            const float4* __restrict__ user,
                            const float4* __restrict__ item) {
    int i = blockIdx.x * blockDim.x + threadIdx.x;
    if (i < N_TOTAL) g_deg[i] = 0;
    if (i < N_F4) {
        const int USER_F4 = (N_USERS * EMB_DIM) / 4;
        float4 v = (i < USER_F4) ? __ldg(&user[i]) : __ldg(&item[i - USER_F4]);
        ((uint2*)g_h0)[i] = pack_h4(v);
    }
    if (blockIdx.x == 0) {
        __shared__ int ok;
        if (threadIdx.x == 0) ok = 1;
        __syncthreads();
        long long v = ei64[threadIdx.x];
        if (v < 0 || v >= N_TOTAL) atomicAnd(&ok, 0);
        __syncthreads();
        if (threadIdx.x == 0) g_idx_is64 = ok;
    }
}

// ---------------------------------------------------------------------------
__global__ void hist_kernel(const void* __restrict__ edge_index) {
    int e = blockIdx.x * blockDim.x + threadIdx.x;
    if (e >= N_EDGES) return;
    int r;
    if (__ldg(&g_idx_is64)) r = (int)__ldg(&((const long long*)edge_index)[e]);
    else                    r = __ldg(&((const int*)edge_index)[e]);
    atomicAdd(&g_deg[r], 1);
}

// ---------------------------------------------------------------------------
__global__ void scan1_kernel() {
    __shared__ int sh[SCAN_BLK];
    int i = blockIdx.x * SCAN_BLK + threadIdx.x;
    int v = (i < N_TOTAL) ? g_deg[i] : 0;
    sh[threadIdx.x] = v;
    __syncthreads();
    for (int off = 1; off < SCAN_BLK; off <<= 1) {
        int t = (threadIdx.x >= off) ? sh[threadIdx.x - off] : 0;
        __syncthreads();
        sh[threadIdx.x] += t;
        __syncthreads();
    }
    if (i < N_TOTAL) g_incl[i] = sh[threadIdx.x];
    if (threadIdx.x == SCAN_BLK - 1) g_partials[blockIdx.x] = sh[SCAN_BLK - 1];
}

__global__ void scan2_kernel() {
    __shared__ int sh[256];
    int t = threadIdx.x;
    int v = (t < N_SCANBLK) ? g_partials[t] : 0;
    sh[t] = v;
    __syncthreads();
    for (int off = 1; off < 256; off <<= 1) {
        int u = (t >= off) ? sh[t - off] : 0;
        __syncthreads();
        sh[t] += u;
        __syncthreads();
    }
    if (t < N_SCANBLK) g_blockoff[t] = sh[t] - v;   // exclusive
}

__global__ void scan3_kernel() {
    int i = blockIdx.x * blockDim.x + threadIdx.x;
    if (i >= N_TOTAL) return;
    int incl = g_incl[i] + g_blockoff[i / SCAN_BLK];
    g_off[i + 1] = incl;
    g_cursor[i]  = incl - g_deg[i];
    if (i == 0) g_off[0] = 0;
}

// ---------------------------------------------------------------------------
__global__ void fill_kernel(const void* __restrict__ edge_index,
                            const float* __restrict__ edge_weight) {
    int e = blockIdx.x * blockDim.x + threadIdx.x;
    if (e >= N_EDGES) return;
    int r, c;
    if (__ldg(&g_idx_is64)) {
        const long long* ei = (const long long*)edge_index;
        r = (int)__ldg(&ei[e]);
        c = (int)__ldg(&ei[N_EDGES + e]);
    } else {
        const int* ei = (const int*)edge_index;
        r = __ldg(&ei[e]);
        c = __ldg(&ei[N_EDGES + e]);
    }
    int p = atomicAdd(&g_cursor[r], 1);
    g_cw[p] = make_int2(c, __float_as_int(__ldg(&edge_weight[e])));
}

// ---------------------------------------------------------------------------
// pull: 8 threads per node, lane j owns 8 features (one uint4 = 4 half2).
// Gather fp16 (16B/lane), accumulate fp32 (8 regs).
// FINAL=0: write fp16 row to dst.
// FINAL=1: out = 0.25 * (x0_fp32 + h1 + h2 + a), fp32 output (2 float4/lane).
// ---------------------------------------------------------------------------
template <int FINAL>
__global__ void pull_kernel(const uint4* __restrict__ src,
                            uint4* __restrict__ dst,
                            const float4* __restrict__ eu,   // x0 user (fp32)
                            const float4* __restrict__ ei,   // x0 item (fp32)
                            const uint4* __restrict__ h1,
                            const uint4* __restrict__ h2,
                            float4* __restrict__ out) {
    int gid = blockIdx.x * blockDim.x + threadIdx.x;
    int n = gid >> 3;
    int j = gid & 7;
    if (n >= N_TOTAL) return;

    int s = __ldg(&g_off[n]);
    int t = __ldg(&g_off[n + 1]);

    float a0 = 0.f, a1 = 0.f, a2 = 0.f, a3 = 0.f;
    float a4 = 0.f, a5 = 0.f, a6 = 0.f, a7 = 0.f;
    int e = s;

#define EDGE_STEP(K)                                                          \
    {                                                                         \
        int2 cw = __ldg(&g_cw[e + K]);                                        \
        float w = __int_as_float(cw.y);                                       \
        uint4 p = __ldg(&src[(long long)cw.x * 8 + j]);                       \
        float2 f0 = __half22float2(*(__half2*)&p.x);                          \
        float2 f1 = __half22float2(*(__half2*)&p.y);                          \
        float2 f2 = __half22float2(*(__half2*)&p.z);                          \
        float2 f3 = __half22float2(*(__half2*)&p.w);                          \
        a0 += f0.x * w; a1 += f0.y * w; a2 += f1.x * w; a3 += f1.y * w;       \
        a4 += f2.x * w; a5 += f2.y * w; a6 += f3.x * w; a7 += f3.y * w;       \
    }

    for (; e + 8 <= t; e += 8) {
        EDGE_STEP(0) EDGE_STEP(1) EDGE_STEP(2) EDGE_STEP(3)
        EDGE_STEP(4) EDGE_STEP(5) EDGE_STEP(6) EDGE_STEP(7)
    }
    for (; e < t; e++) {
        EDGE_STEP(0)
    }
#undef EDGE_STEP

    long long oi = (long long)n * 8 + j;
    if (FINAL) {
        long long fi = (long long)n * 16 + 2 * j;        // float4 index
        float4 x0a, x0b;
        if (n < N_USERS) {
            x0a = __ldg(&eu[fi]);
            x0b = __ldg(&eu[fi + 1]);
        } else {
            long long ii = (long long)(n - N_USERS) * 16 + 2 * j;
            x0a = __ldg(&ei[ii]);
            x0b = __ldg(&ei[ii + 1]);
        }
        uint4 p1 = __ldg(&h1[oi]);
        uint4 p2 = __ldg(&h2[oi]);
        float2 u0 = __half22float2(*(__half2*)&p1.x);
        float2 u1 = __half22float2(*(__half2*)&p1.y);
        float2 u2 = __half22float2(*(__half2*)&p1.z);
        float2 u3 = __half22float2(*(__half2*)&p1.w);
        float2 v0 = __half22float2(*(__half2*)&p2.x);
        float2 v1 = __half22float2(*(__half2*)&p2.y);
        float2 v2 = __half22float2(*(__half2*)&p2.z);
        float2 v3 = __half22float2(*(__half2*)&p2.w);
        out[fi]     = make_float4((x0a.x + u0.x + v0.x + a0) * 0.25f,
                                  (x0a.y + u0.y + v0.y + a1) * 0.25f,
                                  (x0a.z + u1.x + v1.x + a2) * 0.25f,
                                  (x0a.w + u1.y + v1.y + a3) * 0.25f);
        out[fi + 1] = make_float4((x0b.x + u2.x + v2.x + a4) * 0.25f,
                                  (x0b.y + u2.y + v2.y + a5) * 0.25f,
                                  (x0b.z + u3.x + v3.x + a6) * 0.25f,
                                  (x0b.w + u3.y + v3.y + a7) * 0.25f);
    } else {
        uint2 lo = pack_h4(make_float4(a0, a1, a2, a3));
        uint2 hi = pack_h4(make_float4(a4, a5, a6, a7));
        dst[oi] = make_uint4(lo.x, lo.y, hi.x, hi.y);
    }
}

extern "C" void kernel_launch(void* const* d_in, const int* in_sizes, int n_in,
                              void* d_out, int out_size) {
    const void* edge_index   = d_in[0];
    const float* edge_weight = (const float*)d_in[1];
    const float4* user_emb   = (const float4*)d_in[2];
    const float4* item_emb   = (const float4*)d_in[3];
    float4* out              = (float4*)d_out;

    uint4 *h0, *h1, *h2;
    cudaGetSymbolAddress((void**)&h0, g_h0);
    cudaGetSymbolAddress((void**)&h1, g_h1);
    cudaGetSymbolAddress((void**)&h2, g_h2);

    const int TPB = 256;
    const int GRID_PREP = (N_F4 + TPB - 1) / TPB;
    const int GRID_EDGE = (N_EDGES + TPB - 1) / TPB;
    const int GRID_NODE = (N_TOTAL + TPB - 1) / TPB;
    const int GRID_PULL = (N_TOTAL * 8 + TPB - 1) / TPB;

    prep_kernel<<<GRID_PREP, TPB>>>((const long long*)edge_index,
                                    user_emb, item_emb);

    // CSR build
    hist_kernel<<<GRID_EDGE, TPB>>>(edge_index);
    scan1_kernel<<<N_SCANBLK, SCAN_BLK>>>();
    scan2_kernel<<<1, 256>>>();
    scan3_kernel<<<GRID_NODE, TPB>>>();
    fill_kernel<<<GRID_EDGE, TPB>>>(edge_index, edge_weight);

    // h1 = A h0 ; h2 = A h1 ; out = 0.25*(x0 + h1 + h2 + A h2)
    pull_kernel<0><<<GRID_PULL, TPB>>>(h0, h1, nullptr, nullptr,
                                       nullptr, nullptr, nullptr);
    pull_kernel<0><<<GRID_PULL, TPB>>>(h1, h2, nullptr, nullptr,
                                       nullptr, nullptr, nullptr);
    pull_kernel<1><<<GRID_PULL, TPB>>>(h2, nullptr, user_emb, item_emb,
                                       h1, h2, out);
}